// round 1
// baseline (speedup 1.0000x reference)
#include <cuda_runtime.h>
#include <math.h>

#define Bsz 64
#define Tsz 2048
#define Dsz 256
#define Hsz 512
#define Gsz 2048
#define NB  128

// Scratch (device globals; no allocations allowed)
__device__ float g_xw[(size_t)Tsz * Gsz * Bsz];   // [t][col][b]  1 GiB
__device__ float g_Ug[NB * Hsz * 16];             // [n][k][c]    4 MB
__device__ float g_h[2 * Hsz * Bsz];              // [parity][j][b]
__device__ unsigned g_bar;

__global__ void reset_bar_k() { g_bar = 0u; }

// Ug[n][k][c] = U[k][gate*512 + 4n + jj], c = gate*4 + jj
__global__ void pack_U_k(const float* __restrict__ U) {
    int idx = blockIdx.x * blockDim.x + threadIdx.x;   // covers 128*512*16
    int c = idx & 15;
    int k = (idx >> 4) & (Hsz - 1);
    int n = idx >> 13;
    g_Ug[idx] = U[k * Gsz + (c >> 2) * Hsz + n * 4 + (c & 3)];
}

// xW GEMM: C[b][col] = sum_k x[b,t,k]*W[k,col] + bias[col], stored [t][col][b]
// grid: (16 colblocks, 2048 t), 256 threads, tile 64b x 128c, BK=32, microtile 4x8
__global__ __launch_bounds__(256, 2) void gemm_xw_k(const float* __restrict__ x,
                                                    const float* __restrict__ W,
                                                    const float* __restrict__ bias) {
    const int t   = blockIdx.y;
    const int cb  = blockIdx.x;
    const int tid = threadIdx.x;
    __shared__ float As[32 * 64];    // [k][b]
    __shared__ float Bs[32 * 128];   // [k][c]
    const int b0 = (tid & 15) * 4;
    const int c0 = (tid >> 4) * 8;
    float acc[4][8];
#pragma unroll
    for (int j = 0; j < 8; ++j) {
        float bv = bias[cb * 128 + c0 + j];
        acc[0][j] = bv; acc[1][j] = bv; acc[2][j] = bv; acc[3][j] = bv;
    }
    const int lb = tid & 63;           // b row for A load
    const int lk = (tid >> 6) * 8;     // k offset for A load
    const int wk = tid >> 3;           // k row for B load
    const int wc = (tid & 7) * 16;     // col offset for B load

    for (int k0 = 0; k0 < Dsz; k0 += 32) {
        const float* xp = x + ((size_t)lb * Tsz + t) * Dsz + k0 + lk;
        float4 a0 = *(const float4*)xp;
        float4 a1 = *(const float4*)(xp + 4);
        As[(lk + 0) * 64 + lb] = a0.x;
        As[(lk + 1) * 64 + lb] = a0.y;
        As[(lk + 2) * 64 + lb] = a0.z;
        As[(lk + 3) * 64 + lb] = a0.w;
        As[(lk + 4) * 64 + lb] = a1.x;
        As[(lk + 5) * 64 + lb] = a1.y;
        As[(lk + 6) * 64 + lb] = a1.z;
        As[(lk + 7) * 64 + lb] = a1.w;
        const float* wp = W + (size_t)(k0 + wk) * Gsz + cb * 128 + wc;
        float4 w0 = ((const float4*)wp)[0];
        float4 w1 = ((const float4*)wp)[1];
        float4 w2 = ((const float4*)wp)[2];
        float4 w3 = ((const float4*)wp)[3];
        ((float4*)&Bs[wk * 128 + wc])[0] = w0;
        ((float4*)&Bs[wk * 128 + wc])[1] = w1;
        ((float4*)&Bs[wk * 128 + wc])[2] = w2;
        ((float4*)&Bs[wk * 128 + wc])[3] = w3;
        __syncthreads();
#pragma unroll
        for (int kk = 0; kk < 32; ++kk) {
            float4 a  = *(const float4*)&As[kk * 64 + b0];
            float4 u0 = *(const float4*)&Bs[kk * 128 + c0];
            float4 u1 = *(const float4*)&Bs[kk * 128 + c0 + 4];
            float av[4] = {a.x, a.y, a.z, a.w};
            float uv[8] = {u0.x, u0.y, u0.z, u0.w, u1.x, u1.y, u1.z, u1.w};
#pragma unroll
            for (int i = 0; i < 4; ++i)
#pragma unroll
                for (int j = 0; j < 8; ++j)
                    acc[i][j] += av[i] * uv[j];
        }
        __syncthreads();
    }
#pragma unroll
    for (int j = 0; j < 8; ++j) {
        float4 v = make_float4(acc[0][j], acc[1][j], acc[2][j], acc[3][j]);
        *(float4*)&g_xw[((size_t)t * Gsz + cb * 128 + c0 + j) * 64 + b0] = v;
    }
}

__device__ __forceinline__ void gsync(unsigned target) {
    __syncthreads();
    if (threadIdx.x == 0) {
        __threadfence();
        atomicAdd(&g_bar, 1u);
        while (*((volatile unsigned*)&g_bar) < target) { }
        __threadfence();
    }
    __syncthreads();
}

// Persistent recurrence: 128 CTAs x 256 threads. CTA n owns hidden j in [4n,4n+4)
// (gate columns {gate*512 + 4n + jj}). Per step: gates(64b x 16c) = h(64x512) @ Ug,
// K split across 4 thread-groups, then CTA-local elementwise update. One grid
// barrier per step; c stays in a register the whole time.
__global__ __launch_bounds__(256, 1) void lstm_rec_k(float* __restrict__ out) {
    const int n   = blockIdx.x;
    const int tid = threadIdx.x;
    const int kg  = tid >> 6;          // K-group 0..3
    const int t64 = tid & 63;
    const int b0  = (t64 & 15) * 4;    // compute-role batch base
    const int c0  = (t64 >> 4) * 4;    // compute-role col base
    const int ub  = tid & 63;          // update-role batch
    const int ujj = tid >> 6;          // update-role hidden-within-CTA
    const int jglob = 4 * n + ujj;

    __shared__ float smem[4 * 32 * 64 + 4 * 32 * 16];  // 40 KB
    float* hs = smem;                  // [kg][32][64]
    float* us = smem + 8192;           // [kg][32][16]
    float* part = smem;                // aliases hs: [kg][16][64]

    // zero h (parity 0) — each CTA zeros its own slice
    g_h[jglob * 64 + ub] = 0.0f;
    float creg = 0.0f, hreg = 0.0f;

    unsigned target = NB;
    gsync(target); target += NB;       // all of h visible before step 0

    const float* Ublk = g_Ug + n * (Hsz * 16);

    for (int step = 0; step < Tsz; ++step) {
        const int p = step & 1;
        const float* hsrc = g_h + p * (Hsz * Bsz);

        // prefetch this step's xW contribution early (hides DRAM latency)
        float xg[4];
#pragma unroll
        for (int gate = 0; gate < 4; ++gate)
            xg[gate] = __ldcs(&g_xw[((size_t)step * Gsz + gate * Hsz + jglob) * 64 + ub]);

        float acc[4][4];
#pragma unroll
        for (int i = 0; i < 4; ++i)
#pragma unroll
            for (int j = 0; j < 4; ++j) acc[i][j] = 0.0f;

#pragma unroll 1
        for (int chunk = 0; chunk < 4; ++chunk) {
            const int kbase = kg * 128 + chunk * 32;
            // stage h chunk (L2 read: .cg — L1 is stale across grid barriers)
            const float4* src4 = (const float4*)(hsrc + kbase * 64);
            float4* dh4 = (float4*)(hs + kg * 2048);
#pragma unroll
            for (int i = 0; i < 8; ++i) dh4[t64 + i * 64] = __ldcg(src4 + t64 + i * 64);
            const float4* su4 = (const float4*)(Ublk + kbase * 16);
            float4* du4 = (float4*)(us + kg * 512);
            du4[t64 * 2]     = su4[t64 * 2];
            du4[t64 * 2 + 1] = su4[t64 * 2 + 1];
            __syncthreads();
#pragma unroll
            for (int kk = 0; kk < 32; ++kk) {
                float4 a = *(const float4*)(hs + kg * 2048 + kk * 64 + b0);
                float4 u = *(const float4*)(us + kg * 512 + kk * 16 + c0);
                acc[0][0] += a.x * u.x; acc[0][1] += a.x * u.y; acc[0][2] += a.x * u.z; acc[0][3] += a.x * u.w;
                acc[1][0] += a.y * u.x; acc[1][1] += a.y * u.y; acc[1][2] += a.y * u.z; acc[1][3] += a.y * u.w;
                acc[2][0] += a.z * u.x; acc[2][1] += a.z * u.y; acc[2][2] += a.z * u.z; acc[2][3] += a.z * u.w;
                acc[3][0] += a.w * u.x; acc[3][1] += a.w * u.y; acc[3][2] += a.w * u.z; acc[3][3] += a.w * u.w;
            }
            __syncthreads();
        }

        // K-group partials -> smem (aliases hs; safe after last sync)
#pragma unroll
        for (int j = 0; j < 4; ++j)
            *(float4*)&part[(kg * 16 + c0 + j) * 64 + b0] =
                make_float4(acc[0][j], acc[1][j], acc[2][j], acc[3][j]);
        __syncthreads();

        // reduce + elementwise update: thread owns (ub, jglob)
        float v[4];
#pragma unroll
        for (int gate = 0; gate < 4; ++gate) {
            int c = gate * 4 + ujj;
            v[gate] = part[(0 * 16 + c) * 64 + ub] + part[(1 * 16 + c) * 64 + ub]
                    + part[(2 * 16 + c) * 64 + ub] + part[(3 * 16 + c) * 64 + ub]
                    + xg[gate];
        }
        float ig = 1.0f / (1.0f + __expf(-v[0]));
        float fg = 1.0f / (1.0f + __expf(-v[1]));
        float gg = tanhf(v[2]);
        float og = 1.0f / (1.0f + __expf(-v[3]));
        creg = fg * creg + ig * gg;
        hreg = og * tanhf(creg);
        g_h[(p ^ 1) * (Hsz * Bsz) + jglob * 64 + ub] = hreg;

        gsync(target); target += NB;
    }

    // output: h then c, each [B][H]
    out[ub * Hsz + jglob] = hreg;
    out[Bsz * Hsz + ub * Hsz + jglob] = creg;
}

extern "C" void kernel_launch(void* const* d_in, const int* in_sizes, int n_in,
                              void* d_out, int out_size) {
    const float* x    = (const float*)d_in[0];
    const float* W    = (const float*)d_in[1];
    const float* U    = (const float*)d_in[2];
    const float* bias = (const float*)d_in[3];
    float* out = (float*)d_out;
    (void)in_sizes; (void)n_in; (void)out_size;

    pack_U_k<<<2048, 512>>>(U);
    dim3 g(16, Tsz);
    gemm_xw_k<<<g, 256>>>(x, W, bias);
    reset_bar_k<<<1, 1>>>();
    lstm_rec_k<<<NB, 256>>>(out);
}

// round 2
// speedup vs baseline: 1.0244x; 1.0244x over previous
#include <cuda_runtime.h>
#include <math.h>

#define Bsz 64
#define Tsz 2048
#define Dsz 256
#define Hsz 512
#define Gsz 2048
#define NB  128

typedef unsigned long long u64;

// ---- packed fp32x2 helpers (Blackwell FFMA2 path, PTX-only) ----
__device__ __forceinline__ u64 ffma2(u64 a, u64 b, u64 c) {
    u64 d;
    asm("fma.rn.f32x2 %0, %1, %2, %3;" : "=l"(d) : "l"(a), "l"(b), "l"(c));
    return d;
}
__device__ __forceinline__ u64 dup2(float x) {
    u64 d;
    asm("mov.b64 %0, {%1, %1};" : "=l"(d) : "r"(__float_as_uint(x)));
    return d;
}
__device__ __forceinline__ float lo2(u64 d) { return __int_as_float((int)(d & 0xffffffffu)); }
__device__ __forceinline__ float hi2(u64 d) { return __int_as_float((int)(d >> 32)); }

// Scratch (device globals; no allocations allowed)
__device__ float g_xw[(size_t)Tsz * Gsz * Bsz];    // [t][col][b]  1 GiB
__device__ float g_Ug[64 * Hsz * 64];              // [cg][k][c-dup 64]  8 MB
__device__ float g_h[2 * Hsz * Bsz];               // [parity][j][b]
__device__ unsigned g_bar;

__global__ void reset_bar_k() { g_bar = 0u; }

// g_Ug[cg][k][2c]=g_Ug[cg][k][2c+1]=U[k][gate*512 + cg*8 + jj], c=gate*8+jj (32 cols/cg)
__global__ void pack_U_k(const float* __restrict__ U) {
    int idx = blockIdx.x * blockDim.x + threadIdx.x;   // 2^21 total
    int c2 = idx & 63;
    int k  = (idx >> 6) & (Hsz - 1);
    int cg = idx >> 15;
    int c  = c2 >> 1;
    g_Ug[idx] = U[k * Gsz + (c >> 3) * Hsz + cg * 8 + (c & 7)];
}

// xW GEMM with FFMA2: C[b][col] = sum_k x[b,t,k]*W[k,col] + bias[col] -> [t][col][b]
// grid (16, 2048), 256 threads, tile 64b x 128c, BK=32, microtile 4b x 8c (c-pairs)
__global__ __launch_bounds__(256, 2) void gemm_xw_k(const float* __restrict__ x,
                                                    const float* __restrict__ W,
                                                    const float* __restrict__ bias) {
    const int t   = blockIdx.y;
    const int cb  = blockIdx.x;
    const int tid = threadIdx.x;
    __shared__ float As[32 * 68];    // [k][b] pad 68
    __shared__ float Bs[32 * 132];   // [k][c] pad 132
    const int b0 = (tid & 15) * 4;
    const int c0 = (tid >> 4) * 8;

    u64 acc[4][4];
    {
        ulonglong2 bb0 = *(const ulonglong2*)(bias + cb * 128 + c0);
        ulonglong2 bb1 = *(const ulonglong2*)(bias + cb * 128 + c0 + 4);
#pragma unroll
        for (int i = 0; i < 4; ++i) {
            acc[i][0] = bb0.x; acc[i][1] = bb0.y;
            acc[i][2] = bb1.x; acc[i][3] = bb1.y;
        }
    }
    const int arow = tid >> 3;          // 0..31 (b row, +32 on pass 1)
    const int af4  = tid & 7;           // 4-float group within 32-k block
    const int wk   = tid >> 3;          // k row for W load
    const int wc   = (tid & 7) * 16;    // col offset for W load

    for (int k0 = 0; k0 < Dsz; k0 += 32) {
#pragma unroll
        for (int pass = 0; pass < 2; ++pass) {
            int b = arow + pass * 32;
            float4 v = *(const float4*)(x + ((size_t)b * Tsz + t) * Dsz + k0 + af4 * 4);
            As[(af4 * 4 + 0) * 68 + b] = v.x;
            As[(af4 * 4 + 1) * 68 + b] = v.y;
            As[(af4 * 4 + 2) * 68 + b] = v.z;
            As[(af4 * 4 + 3) * 68 + b] = v.w;
        }
        const float* wp = W + (size_t)(k0 + wk) * Gsz + cb * 128 + wc;
        float4 w0 = ((const float4*)wp)[0];
        float4 w1 = ((const float4*)wp)[1];
        float4 w2 = ((const float4*)wp)[2];
        float4 w3 = ((const float4*)wp)[3];
        *(float4*)&Bs[wk * 132 + wc + 0]  = w0;
        *(float4*)&Bs[wk * 132 + wc + 4]  = w1;
        *(float4*)&Bs[wk * 132 + wc + 8]  = w2;
        *(float4*)&Bs[wk * 132 + wc + 12] = w3;
        __syncthreads();
#pragma unroll
        for (int kk = 0; kk < 32; ++kk) {
            float4 a = *(const float4*)&As[kk * 68 + b0];
            ulonglong2 u01 = *(const ulonglong2*)&Bs[kk * 132 + c0];
            ulonglong2 u23 = *(const ulonglong2*)&Bs[kk * 132 + c0 + 4];
            u64 a0 = dup2(a.x), a1 = dup2(a.y), a2 = dup2(a.z), a3 = dup2(a.w);
            acc[0][0] = ffma2(a0, u01.x, acc[0][0]);
            acc[1][0] = ffma2(a1, u01.x, acc[1][0]);
            acc[2][0] = ffma2(a2, u01.x, acc[2][0]);
            acc[3][0] = ffma2(a3, u01.x, acc[3][0]);
            acc[0][1] = ffma2(a0, u01.y, acc[0][1]);
            acc[1][1] = ffma2(a1, u01.y, acc[1][1]);
            acc[2][1] = ffma2(a2, u01.y, acc[2][1]);
            acc[3][1] = ffma2(a3, u01.y, acc[3][1]);
            acc[0][2] = ffma2(a0, u23.x, acc[0][2]);
            acc[1][2] = ffma2(a1, u23.x, acc[1][2]);
            acc[2][2] = ffma2(a2, u23.x, acc[2][2]);
            acc[3][2] = ffma2(a3, u23.x, acc[3][2]);
            acc[0][3] = ffma2(a0, u23.y, acc[0][3]);
            acc[1][3] = ffma2(a1, u23.y, acc[1][3]);
            acc[2][3] = ffma2(a2, u23.y, acc[2][3]);
            acc[3][3] = ffma2(a3, u23.y, acc[3][3]);
        }
        __syncthreads();
    }
#pragma unroll
    for (int jp = 0; jp < 4; ++jp) {
        float4 lo = make_float4(lo2(acc[0][jp]), lo2(acc[1][jp]), lo2(acc[2][jp]), lo2(acc[3][jp]));
        float4 hi = make_float4(hi2(acc[0][jp]), hi2(acc[1][jp]), hi2(acc[2][jp]), hi2(acc[3][jp]));
        size_t base = (size_t)t * Gsz + cb * 128;
        *(float4*)&g_xw[(base + c0 + 2 * jp) * 64 + b0]     = lo;
        *(float4*)&g_xw[(base + c0 + 2 * jp + 1) * 64 + b0] = hi;
    }
}

__device__ __forceinline__ void gsync(unsigned target) {
    __syncthreads();
    if (threadIdx.x == 0) {
        __threadfence();
        atomicAdd(&g_bar, 1u);
        while (*((volatile unsigned*)&g_bar) < target) { }
        __threadfence();
    }
    __syncthreads();
}

// Persistent recurrence, FFMA2 version.
// 128 CTAs = (b-half bh in {0,1}) x (64 col-groups cg, each owning 8 hidden units
// = 32 gate cols). U slice (dup'd pairs) resident in smem for all steps.
// 256 threads = 4 K-groups x 64; per step: out tile 32b x 32c per group, K=128 each,
// staged h chunks (32 k) double-buffered, then cross-group reduce + update.
// Dyn smem: Us[512][64] (128KB) + hs[2][4][32][40] (40KB); part aliases hs buf0.
#define REC_SMEM_FLOATS (32768 + 2 * 4 * 32 * 40)

__global__ __launch_bounds__(256, 1) void lstm_rec_k(float* __restrict__ out) {
    extern __shared__ float sm[];
    const int n   = blockIdx.x;
    const int tid = threadIdx.x;
    const int bh  = n & 1;
    const int cg  = n >> 1;
    const int kg  = tid >> 6;
    const int t64 = tid & 63;
    const int b0  = (t64 & 7) * 4;     // compute: batch base (within half)
    const int c0  = (t64 >> 3) * 4;    // compute: col base (0..28)
    const int ub  = tid & 31;          // update: batch within half
    const int ujj = (tid >> 5) & 7;    // update: hidden-within-cg
    const int jbase = cg * 8;
    const int f4  = t64 & 7;           // stage: float4 slot
    const int r0  = t64 >> 3;          // stage: row base

    float* Us = sm;                    // [512][64] dup'd
    float* hsb = sm + 32768;           // [2][4][32][40]
    float* part = sm + 32768;          // aliases buf0: [4][32c][32b]

    // U slice resident load (once)
    {
        const float4* Usrc = (const float4*)(g_Ug + (size_t)cg * 32768);
        float4* Udst = (float4*)Us;
        for (int i = tid; i < 8192; i += 256) Udst[i] = Usrc[i];
    }

    // zero h parity 0 (this CTA's slice)
    g_h[(jbase + ujj) * 64 + bh * 32 + ub] = 0.0f;
    float creg = 0.0f, hreg = 0.0f;

    unsigned target = NB;
    gsync(target); target += NB;       // h zeroed + Us loaded (bar inside)

    for (int step = 0; step < Tsz; ++step) {
        const int p = step & 1;
        const float* hsrc = g_h + p * (Hsz * Bsz);

        // prefetch this thread's xW contribution (update role)
        float xg[4];
#pragma unroll
        for (int gate = 0; gate < 4; ++gate)
            xg[gate] = __ldcs(&g_xw[((size_t)step * Gsz + gate * Hsz + jbase + ujj) * 64 + bh * 32 + ub]);

        u64 acc[2][4];
#pragma unroll
        for (int i = 0; i < 2; ++i)
#pragma unroll
            for (int j = 0; j < 4; ++j) acc[i][j] = 0ull;

        // stage chunk 0 -> buf 0
        {
            const int kr0 = kg * 128;
            float* dst = hsb + kg * 1280;
#pragma unroll
            for (int pass = 0; pass < 4; ++pass) {
                int r = r0 + pass * 8;
                float4 v = __ldcg((const float4*)(hsrc + (kr0 + r) * 64 + bh * 32) + f4);
                *(float4*)(dst + r * 40 + f4 * 4) = v;
            }
        }
        __syncthreads();

#pragma unroll 1
        for (int ch = 0; ch < 4; ++ch) {
            if (ch < 3) {  // stage next chunk into other buffer
                const int kr0 = kg * 128 + (ch + 1) * 32;
                float* dst = hsb + ((ch + 1) & 1) * 5120 + kg * 1280;
#pragma unroll
                for (int pass = 0; pass < 4; ++pass) {
                    int r = r0 + pass * 8;
                    float4 v = __ldcg((const float4*)(hsrc + (kr0 + r) * 64 + bh * 32) + f4);
                    *(float4*)(dst + r * 40 + f4 * 4) = v;
                }
            }
            const float* hcur = hsb + (ch & 1) * 5120 + kg * 1280;
            const float* Uk = Us + (size_t)(kg * 128 + ch * 32) * 64;
#pragma unroll
            for (int kk = 0; kk < 32; ++kk) {
                ulonglong2 hp  = *(const ulonglong2*)(hcur + kk * 40 + b0);
                ulonglong2 u01 = *(const ulonglong2*)(Uk + kk * 64 + 2 * c0);
                ulonglong2 u23 = *(const ulonglong2*)(Uk + kk * 64 + 2 * c0 + 4);
                acc[0][0] = ffma2(hp.x, u01.x, acc[0][0]);
                acc[1][0] = ffma2(hp.y, u01.x, acc[1][0]);
                acc[0][1] = ffma2(hp.x, u01.y, acc[0][1]);
                acc[1][1] = ffma2(hp.y, u01.y, acc[1][1]);
                acc[0][2] = ffma2(hp.x, u23.x, acc[0][2]);
                acc[1][2] = ffma2(hp.y, u23.x, acc[1][2]);
                acc[0][3] = ffma2(hp.x, u23.y, acc[0][3]);
                acc[1][3] = ffma2(hp.y, u23.y, acc[1][3]);
            }
            __syncthreads();
        }

        // write K-group partials (part aliases buf0; last compute used buf1)
#pragma unroll
        for (int j = 0; j < 4; ++j)
            *(ulonglong2*)&part[kg * 1024 + (c0 + j) * 32 + b0] =
                make_ulonglong2(acc[0][j], acc[1][j]);
        __syncthreads();

        // reduce + elementwise update
        float v[4];
#pragma unroll
        for (int gate = 0; gate < 4; ++gate) {
            const float* pp = part + (gate * 8 + ujj) * 32 + ub;
            v[gate] = xg[gate] + pp[0] + pp[1024] + pp[2048] + pp[3072];
        }
        float ig = 1.0f / (1.0f + __expf(-v[0]));
        float fg = 1.0f / (1.0f + __expf(-v[1]));
        float gg = tanhf(v[2]);
        float og = 1.0f / (1.0f + __expf(-v[3]));
        creg = fg * creg + ig * gg;
        hreg = og * tanhf(creg);
        g_h[(p ^ 1) * (Hsz * Bsz) + (jbase + ujj) * 64 + bh * 32 + ub] = hreg;

        gsync(target); target += NB;
    }

    // output: h then c, each [B][H]
    out[(bh * 32 + ub) * Hsz + jbase + ujj] = hreg;
    out[Bsz * Hsz + (bh * 32 + ub) * Hsz + jbase + ujj] = creg;
}

extern "C" void kernel_launch(void* const* d_in, const int* in_sizes, int n_in,
                              void* d_out, int out_size) {
    const float* x    = (const float*)d_in[0];
    const float* W    = (const float*)d_in[1];
    const float* U    = (const float*)d_in[2];
    const float* bias = (const float*)d_in[3];
    float* out = (float*)d_out;
    (void)in_sizes; (void)n_in; (void)out_size;

    static int smem_set = 0;
    if (!smem_set) {
        cudaFuncSetAttribute(lstm_rec_k, cudaFuncAttributeMaxDynamicSharedMemorySize,
                             REC_SMEM_FLOATS * 4);
        smem_set = 1;
    }

    pack_U_k<<<4096, 512>>>(U);
    dim3 g(16, Tsz);
    gemm_xw_k<<<g, 256>>>(x, W, bias);
    reset_bar_k<<<1, 1>>>();
    lstm_rec_k<<<NB, 256, REC_SMEM_FLOATS * 4>>>(out);
}

// round 3
// speedup vs baseline: 1.2763x; 1.2460x over previous
#include <cuda_runtime.h>
#include <math.h>

#define Bsz 64
#define Tsz 2048
#define Dsz 256
#define Hsz 512
#define Gsz 2048
#define NB  128

typedef unsigned long long u64;

// ---- packed fp32x2 helpers (Blackwell FFMA2, PTX-only) ----
__device__ __forceinline__ u64 ffma2(u64 a, u64 b, u64 c) {
    u64 d;
    asm("fma.rn.f32x2 %0, %1, %2, %3;" : "=l"(d) : "l"(a), "l"(b), "l"(c));
    return d;
}
__device__ __forceinline__ u64 dup2(float x) {
    u64 d;
    asm("mov.b64 %0, {%1, %1};" : "=l"(d) : "r"(__float_as_uint(x)));
    return d;
}
__device__ __forceinline__ float lo2(u64 d) { return __int_as_float((int)(unsigned)(d & 0xffffffffu)); }
__device__ __forceinline__ float hi2(u64 d) { return __int_as_float((int)(unsigned)(d >> 32)); }

// Scratch (device globals)
__device__ float g_xw[(size_t)Tsz * Gsz * Bsz];    // [t][col][b]  1 GiB
__device__ float g_Up[64 * Hsz * 32];              // [cg][k][c]   4 MB (un-dup'd)
__device__ float g_h[2 * Hsz * Bsz];               // [parity][j][b]
__device__ unsigned g_bar;

__global__ void reset_bar_k() { g_bar = 0u; }

// g_Up[cg][k][c] = U[k][gate*512 + cg*8 + jj], c = gate*8 + jj  (32 cols per cg)
__global__ void pack_U_k(const float* __restrict__ U) {
    int idx = blockIdx.x * blockDim.x + threadIdx.x;   // 2^20 total
    int c  = idx & 31;
    int k  = (idx >> 5) & (Hsz - 1);
    int cg = idx >> 14;
    g_Up[idx] = U[k * Gsz + (c >> 3) * Hsz + cg * 8 + (c & 7)];
}

// xW GEMM with FFMA2: C[b][col] = sum_k x[b,t,k]*W[k,col] + bias[col] -> [t][col][b]
__global__ __launch_bounds__(256, 2) void gemm_xw_k(const float* __restrict__ x,
                                                    const float* __restrict__ W,
                                                    const float* __restrict__ bias) {
    const int t   = blockIdx.y;
    const int cb  = blockIdx.x;
    const int tid = threadIdx.x;
    __shared__ float As[32 * 68];
    __shared__ float Bs[32 * 132];
    const int b0 = (tid & 15) * 4;
    const int c0 = (tid >> 4) * 8;

    u64 acc[4][4];
    {
        ulonglong2 bb0 = *(const ulonglong2*)(bias + cb * 128 + c0);
        ulonglong2 bb1 = *(const ulonglong2*)(bias + cb * 128 + c0 + 4);
#pragma unroll
        for (int i = 0; i < 4; ++i) {
            acc[i][0] = bb0.x; acc[i][1] = bb0.y;
            acc[i][2] = bb1.x; acc[i][3] = bb1.y;
        }
    }
    const int arow = tid >> 3;
    const int af4  = tid & 7;
    const int wk   = tid >> 3;
    const int wc   = (tid & 7) * 16;

    for (int k0 = 0; k0 < Dsz; k0 += 32) {
#pragma unroll
        for (int pass = 0; pass < 2; ++pass) {
            int b = arow + pass * 32;
            float4 v = *(const float4*)(x + ((size_t)b * Tsz + t) * Dsz + k0 + af4 * 4);
            As[(af4 * 4 + 0) * 68 + b] = v.x;
            As[(af4 * 4 + 1) * 68 + b] = v.y;
            As[(af4 * 4 + 2) * 68 + b] = v.z;
            As[(af4 * 4 + 3) * 68 + b] = v.w;
        }
        const float* wp = W + (size_t)(k0 + wk) * Gsz + cb * 128 + wc;
        float4 w0 = ((const float4*)wp)[0];
        float4 w1 = ((const float4*)wp)[1];
        float4 w2 = ((const float4*)wp)[2];
        float4 w3 = ((const float4*)wp)[3];
        *(float4*)&Bs[wk * 132 + wc + 0]  = w0;
        *(float4*)&Bs[wk * 132 + wc + 4]  = w1;
        *(float4*)&Bs[wk * 132 + wc + 8]  = w2;
        *(float4*)&Bs[wk * 132 + wc + 12] = w3;
        __syncthreads();
#pragma unroll
        for (int kk = 0; kk < 32; ++kk) {
            float4 a = *(const float4*)&As[kk * 68 + b0];
            ulonglong2 u01 = *(const ulonglong2*)&Bs[kk * 132 + c0];
            ulonglong2 u23 = *(const ulonglong2*)&Bs[kk * 132 + c0 + 4];
            u64 a0 = dup2(a.x), a1 = dup2(a.y), a2 = dup2(a.z), a3 = dup2(a.w);
            acc[0][0] = ffma2(a0, u01.x, acc[0][0]);
            acc[1][0] = ffma2(a1, u01.x, acc[1][0]);
            acc[2][0] = ffma2(a2, u01.x, acc[2][0]);
            acc[3][0] = ffma2(a3, u01.x, acc[3][0]);
            acc[0][1] = ffma2(a0, u01.y, acc[0][1]);
            acc[1][1] = ffma2(a1, u01.y, acc[1][1]);
            acc[2][1] = ffma2(a2, u01.y, acc[2][1]);
            acc[3][1] = ffma2(a3, u01.y, acc[3][1]);
            acc[0][2] = ffma2(a0, u23.x, acc[0][2]);
            acc[1][2] = ffma2(a1, u23.x, acc[1][2]);
            acc[2][2] = ffma2(a2, u23.x, acc[2][2]);
            acc[3][2] = ffma2(a3, u23.x, acc[3][2]);
            acc[0][3] = ffma2(a0, u23.y, acc[0][3]);
            acc[1][3] = ffma2(a1, u23.y, acc[1][3]);
            acc[2][3] = ffma2(a2, u23.y, acc[2][3]);
            acc[3][3] = ffma2(a3, u23.y, acc[3][3]);
        }
        __syncthreads();
    }
#pragma unroll
    for (int jp = 0; jp < 4; ++jp) {
        float4 lo = make_float4(lo2(acc[0][jp]), lo2(acc[1][jp]), lo2(acc[2][jp]), lo2(acc[3][jp]));
        float4 hi = make_float4(hi2(acc[0][jp]), hi2(acc[1][jp]), hi2(acc[2][jp]), hi2(acc[3][jp]));
        size_t base = (size_t)t * Gsz + cb * 128;
        *(float4*)&g_xw[(base + c0 + 2 * jp) * 64 + b0]     = lo;
        *(float4*)&g_xw[(base + c0 + 2 * jp + 1) * 64 + b0] = hi;
    }
}

__device__ __forceinline__ void gsync(unsigned target) {
    __syncthreads();
    if (threadIdx.x == 0) {
        __threadfence();
        atomicAdd(&g_bar, 1u);
        while (*((volatile unsigned*)&g_bar) < target) { }
        __threadfence();
    }
    __syncthreads();
}

// Persistent recurrence, 8x8-tile FFMA2 version.
// 128 CTAs = (b-half bh) x (64 col-groups cg: 8 hidden units = 32 gate cols).
// 256 threads = 16 K-groups x 16; K-group kg owns k in {kg, kg+16, kg+32, ...}
// (interleaved -> adjacent smem rows inside a warp -> conflict-free banks).
// Thread tile 8b x 8c: 32 FFMA2 per kk from 32B h + 32B u (r = 1.0 FMA/byte).
// Smem: Us[512][36] resident, hs[512][36] staged per step (aliased by K-partials),
// red[32][36] reduced gates.
#define REC_SMEM_FLOATS (18432 + 18432 + 1152)

__global__ __launch_bounds__(256, 1) void lstm_rec_k(float* __restrict__ out) {
    extern __shared__ float sm[];
    float* Us  = sm;            // [512][36]
    float* hs  = sm + 18432;    // [512][36]; partials alias: [kg*32+c][36]
    float* red = sm + 36864;    // [32][36]

    const int n   = blockIdx.x;
    const int tid = threadIdx.x;
    const int bh  = n & 1;
    const int cg  = n >> 1;
    const int kg  = tid >> 4;          // 0..15
    const int t16 = tid & 15;
    const int b0  = (t16 & 3) * 8;     // 0,8,16,24
    const int c0  = (t16 >> 2) * 8;    // 0,8,16,24
    const int ub  = tid & 31;          // update role: batch within half
    const int ujj = tid >> 5;          // update role: hidden-within-cg 0..7
    const int jbase = cg * 8;

    // resident U slice (un-dup'd)
    for (int i = tid; i < 4096; i += 256) {
        int k = i >> 3, q = i & 7;
        *(float4*)&Us[k * 36 + q * 4] = *(const float4*)&g_Up[(size_t)cg * 16384 + k * 32 + q * 4];
    }

    // zero h parity 0 (this CTA's slice)
    g_h[(jbase + ujj) * 64 + bh * 32 + ub] = 0.0f;
    float creg = 0.0f, hreg = 0.0f;

    unsigned target = NB;
    gsync(target); target += NB;

    for (int step = 0; step < Tsz; ++step) {
        const int p = step & 1;
        const float* hsrc = g_h + p * (Hsz * Bsz);

        // prefetch this thread's xW contribution (update role)
        float xg[4];
#pragma unroll
        for (int g = 0; g < 4; ++g)
            xg[g] = __ldcs(&g_xw[((size_t)step * Gsz + g * Hsz + jbase + ujj) * 64 + bh * 32 + ub]);

        // stage chunk 0 (k rows [0,128))
        float4 pv[4];
#pragma unroll
        for (int m = 0; m < 4; ++m) {
            int idx = tid + 256 * m; int r = idx >> 3, q = idx & 7;
            pv[m] = __ldcg((const float4*)(hsrc + r * 64 + bh * 32) + q);
        }
#pragma unroll
        for (int m = 0; m < 4; ++m) {
            int idx = tid + 256 * m; int r = idx >> 3, q = idx & 7;
            *(float4*)&hs[r * 36 + q * 4] = pv[m];
        }
        __syncthreads();

        u64 acc[4][8];
#pragma unroll
        for (int i = 0; i < 4; ++i)
#pragma unroll
            for (int j = 0; j < 8; ++j) acc[i][j] = 0ull;

#pragma unroll 1
        for (int ch = 0; ch < 4; ++ch) {
            if (ch < 3) {   // prefetch next chunk into registers (hidden under compute)
#pragma unroll
                for (int m = 0; m < 4; ++m) {
                    int idx = tid + 256 * m; int r = 128 * (ch + 1) + (idx >> 3), q = idx & 7;
                    pv[m] = __ldcg((const float4*)(hsrc + r * 64 + bh * 32) + q);
                }
            }
#pragma unroll
            for (int i = 0; i < 8; ++i) {
                int k = kg + ((ch << 3) + i) * 16;
                ulonglong2 hA = *(const ulonglong2*)&hs[k * 36 + b0];
                ulonglong2 hB = *(const ulonglong2*)&hs[k * 36 + b0 + 4];
                float4 uA = *(const float4*)&Us[k * 36 + c0];
                float4 uB = *(const float4*)&Us[k * 36 + c0 + 4];
                u64 ud;
                ud = dup2(uA.x);
                acc[0][0] = ffma2(hA.x, ud, acc[0][0]); acc[1][0] = ffma2(hA.y, ud, acc[1][0]);
                acc[2][0] = ffma2(hB.x, ud, acc[2][0]); acc[3][0] = ffma2(hB.y, ud, acc[3][0]);
                ud = dup2(uA.y);
                acc[0][1] = ffma2(hA.x, ud, acc[0][1]); acc[1][1] = ffma2(hA.y, ud, acc[1][1]);
                acc[2][1] = ffma2(hB.x, ud, acc[2][1]); acc[3][1] = ffma2(hB.y, ud, acc[3][1]);
                ud = dup2(uA.z);
                acc[0][2] = ffma2(hA.x, ud, acc[0][2]); acc[1][2] = ffma2(hA.y, ud, acc[1][2]);
                acc[2][2] = ffma2(hB.x, ud, acc[2][2]); acc[3][2] = ffma2(hB.y, ud, acc[3][2]);
                ud = dup2(uA.w);
                acc[0][3] = ffma2(hA.x, ud, acc[0][3]); acc[1][3] = ffma2(hA.y, ud, acc[1][3]);
                acc[2][3] = ffma2(hB.x, ud, acc[2][3]); acc[3][3] = ffma2(hB.y, ud, acc[3][3]);
                ud = dup2(uB.x);
                acc[0][4] = ffma2(hA.x, ud, acc[0][4]); acc[1][4] = ffma2(hA.y, ud, acc[1][4]);
                acc[2][4] = ffma2(hB.x, ud, acc[2][4]); acc[3][4] = ffma2(hB.y, ud, acc[3][4]);
                ud = dup2(uB.y);
                acc[0][5] = ffma2(hA.x, ud, acc[0][5]); acc[1][5] = ffma2(hA.y, ud, acc[1][5]);
                acc[2][5] = ffma2(hB.x, ud, acc[2][5]); acc[3][5] = ffma2(hB.y, ud, acc[3][5]);
                ud = dup2(uB.z);
                acc[0][6] = ffma2(hA.x, ud, acc[0][6]); acc[1][6] = ffma2(hA.y, ud, acc[1][6]);
                acc[2][6] = ffma2(hB.x, ud, acc[2][6]); acc[3][6] = ffma2(hB.y, ud, acc[3][6]);
                ud = dup2(uB.w);
                acc[0][7] = ffma2(hA.x, ud, acc[0][7]); acc[1][7] = ffma2(hA.y, ud, acc[1][7]);
                acc[2][7] = ffma2(hB.x, ud, acc[2][7]); acc[3][7] = ffma2(hB.y, ud, acc[3][7]);
            }
            if (ch < 3) {
#pragma unroll
                for (int m = 0; m < 4; ++m) {
                    int idx = tid + 256 * m; int r = 128 * (ch + 1) + (idx >> 3), q = idx & 7;
                    *(float4*)&hs[r * 36 + q * 4] = pv[m];
                }
            }
            __syncthreads();
        }

        // K-group partials into hs alias: row = kg*32 + c
#pragma unroll
        for (int j = 0; j < 8; ++j) {
            int row = kg * 32 + c0 + j;
            *(ulonglong2*)&hs[row * 36 + b0]     = make_ulonglong2(acc[0][j], acc[1][j]);
            *(ulonglong2*)&hs[row * 36 + b0 + 4] = make_ulonglong2(acc[2][j], acc[3][j]);
        }
        __syncthreads();

        // reduce 16 partials
        {
            int c = tid >> 3, bq = (tid & 7) * 4;
            float4 s = *(const float4*)&hs[c * 36 + bq];
#pragma unroll
            for (int g2 = 1; g2 < 16; ++g2) {
                float4 v = *(const float4*)&hs[(g2 * 32 + c) * 36 + bq];
                s.x += v.x; s.y += v.y; s.z += v.z; s.w += v.w;
            }
            *(float4*)&red[c * 36 + bq] = s;
        }
        __syncthreads();

        // elementwise update (thread owns (ub, jbase+ujj))
        float v0 = red[(0 * 8 + ujj) * 36 + ub] + xg[0];
        float v1 = red[(1 * 8 + ujj) * 36 + ub] + xg[1];
        float v2 = red[(2 * 8 + ujj) * 36 + ub] + xg[2];
        float v3 = red[(3 * 8 + ujj) * 36 + ub] + xg[3];
        float ig = 1.0f / (1.0f + __expf(-v0));
        float fg = 1.0f / (1.0f + __expf(-v1));
        float gg = tanhf(v2);
        float og = 1.0f / (1.0f + __expf(-v3));
        creg = fg * creg + ig * gg;
        hreg = og * tanhf(creg);
        g_h[(p ^ 1) * (Hsz * Bsz) + (jbase + ujj) * 64 + bh * 32 + ub] = hreg;

        gsync(target); target += NB;
    }

    out[(bh * 32 + ub) * Hsz + jbase + ujj] = hreg;
    out[Bsz * Hsz + (bh * 32 + ub) * Hsz + jbase + ujj] = creg;
}

extern "C" void kernel_launch(void* const* d_in, const int* in_sizes, int n_in,
                              void* d_out, int out_size) {
    const float* x    = (const float*)d_in[0];
    const float* W    = (const float*)d_in[1];
    const float* U    = (const float*)d_in[2];
    const float* bias = (const float*)d_in[3];
    float* out = (float*)d_out;
    (void)in_sizes; (void)n_in; (void)out_size;

    static int smem_set = 0;
    if (!smem_set) {
        cudaFuncSetAttribute(lstm_rec_k, cudaFuncAttributeMaxDynamicSharedMemorySize,
                             REC_SMEM_FLOATS * 4);
        smem_set = 1;
    }

    pack_U_k<<<2048, 512>>>(U);
    dim3 g(16, Tsz);
    gemm_xw_k<<<g, 256>>>(x, W, bias);
    reset_bar_k<<<1, 1>>>();
    lstm_rec_k<<<NB, 256, REC_SMEM_FLOATS * 4>>>(out);
}